// round 6
// baseline (speedup 1.0000x reference)
#include <cuda_runtime.h>
#include <cuda_bf16.h>
#include <cuda_fp16.h>
#include <cstdint>

// VQVAE nearest-codebook: bf16 mma.sync fast scores + warp-parallel exact fp32 rescore.
// z: [131072, 64] fp32, codebook: [512, 64] fp32. out = (gather, gather).

#define Dm 64
#define Kc 512
#define ROWS_CTA 512
#define THREADS 1024
#define NTILES 64
#define MARGIN 2e-3f
#define PRUNE_SLACK 5e-4f
#define QCAP 128

__device__ float g_ee[Kc];            // exact sequential ||e_j||^2
__device__ unsigned g_cbw[Kc * 32];   // codebook rows, bf16x2 words, B-pair permuted

// ---- smem layout (bytes) ----
#define SM_ZBW  0                      // 512 x 36 u32 bf16x2(-2z), pitch 36      73728
#define SM_BSW  73728                  // 512 x 40 u32 codebook (pitch 40)        81920
#define SM_TMIN 155648                 // 32 warps x 64 tiles x 8 rg, fp16        32768
#define SM_EEF  188416                 // 512 f32 exact ee                         2048
#define SM_ZZS  190464                 // 512 f32 exact zz                         2048
#define SM_MINR 192512                 // 512 u64 (score_bits<<32 | j)             4096
#define SM_QCNT 196608                 // 32 i32                                    128
#define SM_QUE  196736                 // 32 x 128 u32 candidates                 16384
#define SM_TOTAL 213120

__global__ void prep_kernel(const float* __restrict__ cb) {
    int j = blockIdx.x * blockDim.x + threadIdx.x;
    if (j < Kc) {
        const float* e = cb + j * Dm;
        float s = 0.0f;
#pragma unroll
        for (int k = 0; k < Dm; ++k) s = __fadd_rn(s, __fmul_rn(e[k], e[k]));
        g_ee[j] = s;
        // permuted store: position p holds original word w = (p&~7) + ((p>>1)&3) + 4*(p&1)
#pragma unroll
        for (int p = 0; p < 32; ++p) {
            int w = (p & ~7) + ((p >> 1) & 3) + 4 * (p & 1);
            __nv_bfloat162 b = __float22bfloat162_rn(make_float2(e[2 * w], e[2 * w + 1]));
            g_cbw[j * 32 + p] = *(unsigned*)&b;
        }
    }
}

__device__ __forceinline__ void mma16816(float& c0, float& c1, float& c2, float& c3,
                                         unsigned a0, unsigned a1, unsigned a2, unsigned a3,
                                         unsigned b0, unsigned b1) {
    asm volatile("mma.sync.aligned.m16n8k16.row.col.f32.bf16.bf16.f32 "
                 "{%0,%1,%2,%3},{%4,%5,%6,%7},{%8,%9},{%0,%1,%2,%3};"
                 : "+f"(c0), "+f"(c1), "+f"(c2), "+f"(c3)
                 : "r"(a0), "r"(a1), "r"(a2), "r"(a3), "r"(b0), "r"(b1));
}

// Exact rescore (sequential fp32, reference rounding) + 64-bit atomicMin commit.
// key = (score_bits<<32)|j: scores > 0 so bit order == value order; ties -> min j.
__device__ __noinline__ void exact_commit(unsigned pk, const float* __restrict__ z,
                                          const float* __restrict__ cb, size_t blockRow,
                                          const float* zzs, const float* eef,
                                          unsigned long long* minr) {
    int row = pk & 511;
    int j = pk >> 9;
    const float4* zp = (const float4*)(z + (blockRow + row) * Dm);
    const float4* ep = (const float4*)(cb + (size_t)j * Dm);
    float dot = 0.0f;
#pragma unroll
    for (int i = 0; i < 16; ++i) {
        float4 a = __ldg(zp + i);
        float4 b = __ldg(ep + i);
        dot = __fmaf_rn(a.x, b.x, dot);
        dot = __fmaf_rn(a.y, b.y, dot);
        dot = __fmaf_rn(a.z, b.z, dot);
        dot = __fmaf_rn(a.w, b.w, dot);
    }
    float sx = __fadd_rn(__fadd_rn(zzs[row], eef[j]), __fmul_rn(-2.0f, dot));
    unsigned long long key = ((unsigned long long)__float_as_uint(sx) << 32) | (unsigned)j;
    atomicMin(minr + row, key);
}

__global__ void __launch_bounds__(THREADS, 1)
vq_kernel(const float* __restrict__ z, const float* __restrict__ cb,
          float* __restrict__ out, long long half) {
    extern __shared__ char sm[];
    unsigned* zbw = (unsigned*)(sm + SM_ZBW);
    unsigned* bsw = (unsigned*)(sm + SM_BSW);
    __half* tminp = (__half*)(sm + SM_TMIN);
    float* eef = (float*)(sm + SM_EEF);
    float* zzs = (float*)(sm + SM_ZZS);
    unsigned long long* minr = (unsigned long long*)(sm + SM_MINR);
    int* qcnt = (int*)(sm + SM_QCNT);
    unsigned* que = (unsigned*)(sm + SM_QUE);

    const int tid = threadIdx.x, lane = tid & 31, wid = tid >> 5;
    const int q = lane & 3, rg = lane >> 2;
    const size_t blockRow = (size_t)blockIdx.x * ROWS_CTA;

    if (tid < 32) qcnt[tid] = 0;

    // ---------------- prolog: split work across the two half-blocks ----------------
    if (tid < ROWS_CTA) {
        minr[tid] = ~0ull;
        const float4* zr = (const float4*)(z + (blockRow + tid) * Dm);
        float4 v[16];
#pragma unroll
        for (int i = 0; i < 16; ++i) v[i] = zr[i];
        float zz = 0.0f;
#pragma unroll
        for (int i = 0; i < 16; ++i) {
            zz = __fadd_rn(zz, __fmul_rn(v[i].x, v[i].x));
            zz = __fadd_rn(zz, __fmul_rn(v[i].y, v[i].y));
            zz = __fadd_rn(zz, __fmul_rn(v[i].z, v[i].z));
            zz = __fadd_rn(zz, __fmul_rn(v[i].w, v[i].w));
        }
        zzs[tid] = zz;
        unsigned p[32];
#pragma unroll
        for (int i = 0; i < 16; ++i) {
            __nv_bfloat162 b0 = __float22bfloat162_rn(make_float2(-2.f * v[i].x, -2.f * v[i].y));
            __nv_bfloat162 b1 = __float22bfloat162_rn(make_float2(-2.f * v[i].z, -2.f * v[i].w));
            p[2 * i] = *(unsigned*)&b0;
            p[2 * i + 1] = *(unsigned*)&b1;
        }
        uint4* d4 = (uint4*)(zbw + tid * 36);
#pragma unroll
        for (int i = 0; i < 8; ++i) d4[i] = make_uint4(p[4 * i], p[4 * i + 1], p[4 * i + 2], p[4 * i + 3]);
    } else {
        int t2 = tid - ROWS_CTA;
        const uint4* src = (const uint4*)g_cbw;
#pragma unroll
        for (int it = 0; it < 8; ++it) {
            int u = t2 + it * 512;               // 0..4095 uint4 chunks
            int r = u >> 3, c4 = u & 7;
            *(uint4*)(bsw + r * 40 + c4 * 4) = src[u];
        }
        if (t2 < Kc) eef[t2] = g_ee[t2];
    }
    __syncthreads();

    // ---------------- A fragments: M=16 per warp (rows ra, ra+8) ----------------
    const int ra = wid * 16 + rg;
    unsigned a[16];
#pragma unroll
    for (int ks = 0; ks < 4; ++ks) {
        int rbase = ra * 36;
        a[ks * 4 + 0] = zbw[rbase + q + ks * 8];
        a[ks * 4 + 1] = zbw[rbase + 8 * 36 + q + ks * 8];
        a[ks * 4 + 2] = zbw[rbase + q + 4 + ks * 8];
        a[ks * 4 + 3] = zbw[rbase + 8 * 36 + q + 4 + ks * 8];
    }
    const float2* ee2p = (const float2*)eef;

    // ---------------- pass 1: fast mins ----------------
    float mr0 = 1e30f, mr1 = 1e30f;
#pragma unroll 2
    for (int t = 0; t < NTILES; ++t) {
        float2 e2 = ee2p[t * 4 + q];
        float c0 = e2.x, c1 = e2.y, c2 = e2.x, c3 = e2.y;
        const unsigned* bp = bsw + (t * 8 + rg) * 40 + 2 * q;
#pragma unroll
        for (int ks = 0; ks < 4; ++ks) {
            uint2 b = *(const uint2*)(bp + ks * 8);
            mma16816(c0, c1, c2, c3, a[ks * 4], a[ks * 4 + 1], a[ks * 4 + 2], a[ks * 4 + 3], b.x, b.y);
        }
        float m01 = fminf(c0, c1), m23 = fminf(c2, c3);
        mr0 = fminf(mr0, m01);
        mr1 = fminf(mr1, m23);
        float tm = fminf(m01, m23);
        tm = fminf(tm, __shfl_xor_sync(0xffffffffu, tm, 1));
        tm = fminf(tm, __shfl_xor_sync(0xffffffffu, tm, 2));
        if (q == 0) tminp[(wid * NTILES + t) * 8 + rg] = __float2half(tm);
    }
    __syncwarp();

#pragma unroll
    for (int off = 1; off < 4; off <<= 1) {
        mr0 = fminf(mr0, __shfl_xor_sync(0xffffffffu, mr0, off));
        mr1 = fminf(mr1, __shfl_xor_sync(0xffffffffu, mr1, off));
    }
    const float t0 = mr0 + MARGIN, t1 = mr1 + MARGIN;
    const float thrq = fmaxf(t0, t1) + PRUNE_SLACK;

    // ---------------- pass 2: pruned recompute, enqueue candidates ----------------
#define PUSH(rowv, jv) do {                                                       \
        unsigned pk_ = (unsigned)(rowv) | ((unsigned)(jv) << 9);                  \
        int qi_ = atomicAdd(qcnt + wid, 1);                                       \
        if (qi_ < QCAP) que[wid * QCAP + qi_] = pk_;                              \
        else exact_commit(pk_, z, cb, blockRow, zzs, eef, minr);                  \
    } while (0)

#pragma unroll 1
    for (int t = 0; t < NTILES; ++t) {
        float tm = __half2float(tminp[(wid * NTILES + t) * 8 + rg]);
        if (!__any_sync(0xffffffffu, tm <= thrq)) continue;

        float2 e2 = ee2p[t * 4 + q];
        float c0 = e2.x, c1 = e2.y, c2 = e2.x, c3 = e2.y;
        const unsigned* bp = bsw + (t * 8 + rg) * 40 + 2 * q;
#pragma unroll
        for (int ks = 0; ks < 4; ++ks) {
            uint2 b = *(const uint2*)(bp + ks * 8);
            mma16816(c0, c1, c2, c3, a[ks * 4], a[ks * 4 + 1], a[ks * 4 + 2], a[ks * 4 + 3], b.x, b.y);
        }
        int jb = t * 8 + 2 * q;
        if (c0 <= t0) PUSH(ra, jb);
        if (c1 <= t0) PUSH(ra, jb + 1);
        if (c2 <= t1) PUSH(ra + 8, jb);
        if (c3 <= t1) PUSH(ra + 8, jb + 1);
    }
#undef PUSH

    // ---------------- drain queue: 32 lanes rescore distinct candidates ----------------
    __syncwarp();
    int n = *(volatile int*)(qcnt + wid);
    if (n > QCAP) n = QCAP;
    for (int base = 0; base < n; base += 32) {
        int k2 = base + lane;
        if (k2 < n) exact_commit(que[wid * QCAP + k2], z, cb, blockRow, zzs, eef, minr);
    }
    __syncthreads();

    // ---------------- gather + write both tuple halves ----------------
    {
        int row = tid >> 1, hh = tid & 1;
        int j = (int)(unsigned)(minr[row] & 0xFFFFFFFFull);
        size_t g = blockRow + row;
        const float4* s4 = (const float4*)(cb + (size_t)j * Dm + hh * 32);
        float4* o1 = (float4*)(out + g * Dm + hh * 32);
        float4* o2 = (half > 0) ? (float4*)(out + half + g * Dm + hh * 32) : nullptr;
#pragma unroll
        for (int i = 0; i < 8; ++i) {
            float4 tv = s4[i];
            o1[i] = tv;
            if (o2) o2[i] = tv;
        }
    }
}

extern "C" void kernel_launch(void* const* d_in, const int* in_sizes, int n_in,
                              void* d_out, int out_size) {
    const float* z = (const float*)d_in[0];
    const float* cb = (const float*)d_in[1];
    float* out = (float*)d_out;
    const int N = in_sizes[0] / Dm;                      // 131072
    long long half = ((long long)out_size >= 2LL * N * Dm) ? (long long)out_size / 2 : 0;

    cudaFuncSetAttribute(vq_kernel, cudaFuncAttributeMaxDynamicSharedMemorySize, SM_TOTAL);
    prep_kernel<<<2, 256>>>(cb);
    vq_kernel<<<N / ROWS_CTA, THREADS, SM_TOTAL>>>(z, cb, out, half);
}